// round 11
// baseline (speedup 1.0000x reference)
#include <cuda_runtime.h>
#include <cuda_fp16.h>
#include <math.h>
#include <stdint.h>

#define NSEQ  4096
#define CDIM  64
#define MT    64
#define KB    128
#define KSPLIT 2
#define KHALF (NSEQ / KSPLIT)      // 2048
#define NBLK  (KHALF / KB)         // 16

// scratch (allocation-free rule -> __device__ globals)
__device__ __half g_xh[2 * NSEQ * CDIM];
__device__ __half g_xl[2 * NSEQ * CDIM];
__device__ float g_norm[2 * NSEQ];                 // ||x_r||^2
__device__ float g_Opart[2 * KSPLIT * NSEQ * CDIM];
__device__ float g_lpart[2 * KSPLIT * NSEQ];

// smem layout (bytes): Q hi/lo 64x128B each; X double-buffered hi/lo 128x128B each
#define QH_OFF 0u
#define QL_OFF 8192u
#define XB_OFF 16384u              // buf b at XB_OFF + b*32768 (hi), +16384 (lo)
#define SMEM_BYTES 81920u

__device__ __forceinline__ uint32_t cvta_smem(const void* p) {
    uint32_t a;
    asm("{ .reg .u64 t; cvta.to.shared.u64 t, %1; cvt.u32.u64 %0, t; }" : "=r"(a) : "l"(p));
    return a;
}
__device__ __forceinline__ void ldsm4(uint32_t addr, uint32_t* r) {
    asm volatile("ldmatrix.sync.aligned.m8n8.x4.shared.b16 {%0,%1,%2,%3}, [%4];"
                 : "=r"(r[0]), "=r"(r[1]), "=r"(r[2]), "=r"(r[3]) : "r"(addr));
}
__device__ __forceinline__ void ldsm4t(uint32_t addr, uint32_t* r) {
    asm volatile("ldmatrix.sync.aligned.m8n8.x4.trans.shared.b16 {%0,%1,%2,%3}, [%4];"
                 : "=r"(r[0]), "=r"(r[1]), "=r"(r[2]), "=r"(r[3]) : "r"(addr));
}
__device__ __forceinline__ void mma16816(float* c, const uint32_t* a, const uint32_t* b) {
    asm volatile("mma.sync.aligned.m16n8k16.row.col.f32.f16.f16.f32 "
                 "{%0,%1,%2,%3}, {%4,%5,%6,%7}, {%8,%9}, {%0,%1,%2,%3};"
                 : "+f"(c[0]), "+f"(c[1]), "+f"(c[2]), "+f"(c[3])
                 : "r"(a[0]), "r"(a[1]), "r"(a[2]), "r"(a[3]), "r"(b[0]), "r"(b[1]));
}
// fp16-accumulator variant for the small GEMM1 correction terms
__device__ __forceinline__ void mma16816h(uint32_t* c, const uint32_t* a, const uint32_t* b) {
    asm volatile("mma.sync.aligned.m16n8k16.row.col.f16.f16.f16.f16 "
                 "{%0,%1}, {%2,%3,%4,%5}, {%6,%7}, {%0,%1};"
                 : "+r"(c[0]), "+r"(c[1])
                 : "r"(a[0]), "r"(a[1]), "r"(a[2]), "r"(a[3]), "r"(b[0]), "r"(b[1]));
}
__device__ __forceinline__ void cp16(uint32_t dst, const void* src) {
    asm volatile("cp.async.cg.shared.global [%0], [%1], 16;" :: "r"(dst), "l"(src));
}
#define CP_COMMIT()  asm volatile("cp.async.commit_group;" ::: "memory")
#define CP_WAIT(n)   asm volatile("cp.async.wait_group %0;" :: "n"(n) : "memory")

// XOR-swizzled byte offset inside a 128B-row tile
__device__ __forceinline__ uint32_t swz(uint32_t tb, int row, int cb) {
    return tb + row * 128 + (((((unsigned)cb >> 4) ^ (row & 7)) << 4) | (cb & 15));
}

// ---- pre-pass: split fp32 x into fp16 hi + lo, and compute row norms ----
__global__ __launch_bounds__(256) void split_kernel(const float* __restrict__ x)
{
    const int i = blockIdx.x * 256 + threadIdx.x;   // 131072 float4s; row = i>>4
    float4 v = ((const float4*)x)[i];
    __half h0 = __float2half_rn(v.x), h1 = __float2half_rn(v.y);
    __half h2 = __float2half_rn(v.z), h3 = __float2half_rn(v.w);
    __half2 H0 = __halves2half2(h0, h1), H1 = __halves2half2(h2, h3);
    __half2 L0 = __floats2half2_rn(v.x - __half2float(h0), v.y - __half2float(h1));
    __half2 L1 = __floats2half2_rn(v.z - __half2float(h2), v.w - __half2float(h3));
    ((uint2*)g_xh)[i] = make_uint2(*(uint32_t*)&H0, *(uint32_t*)&H1);
    ((uint2*)g_xl)[i] = make_uint2(*(uint32_t*)&L0, *(uint32_t*)&L1);
    // row norm: 16 consecutive lanes share a row
    float nsq = v.x * v.x + v.y * v.y + v.z * v.z + v.w * v.w;
    #pragma unroll
    for (int s = 1; s < 16; s <<= 1)
        nsq += __shfl_xor_sync(0xffffffffu, nsq, s);
    if ((i & 15) == 0) g_norm[i >> 4] = nsq;
}

__global__ __launch_bounds__(128, 2) void attn_main()
{
    extern __shared__ char sm[];
    const uint32_t sb = cvta_smem(sm);
    const int tid = threadIdx.x, lane = tid & 31, w = tid >> 5;
    const int qb = blockIdx.x * MT, b = blockIdx.y, kh = blockIdx.z;
    const __half* xh = g_xh + (size_t)b * NSEQ * CDIM;
    const __half* xl = g_xl + (size_t)b * NSEQ * CDIM;

    // prologue: Q hi/lo + X block 0 via cp.async (one group)
    {
        const int row = tid >> 1, h = tid & 1;
        #pragma unroll
        for (int i = 0; i < 4; ++i) {
            const int cb = h * 64 + i * 16;     // byte col within 128B row
            cp16(swz(sb + QH_OFF, row, cb), xh + (size_t)(qb + row) * CDIM + h * 32 + i * 8);
            cp16(swz(sb + QL_OFF, row, cb), xl + (size_t)(qb + row) * CDIM + h * 32 + i * 8);
        }
        const size_t xrow = (size_t)(kh * KHALF + tid) * CDIM;
        #pragma unroll
        for (int i = 0; i < 8; ++i) {
            cp16(swz(sb + XB_OFF, tid, i * 16), xh + xrow + i * 8);
            cp16(swz(sb + XB_OFF + 16384u, tid, i * 16), xl + xrow + i * 8);
        }
        CP_COMMIT();
    }

    const int r0 = w * 16;
    const int g = lane >> 3, lr = lane & 7;

    // static per-row max: M = ||x_r||^2 + 2 (diag-dominant bound; margin for fp16 headroom)
    const float mneg0 = -(g_norm[b * NSEQ + qb + r0 + (lane >> 2)] + 2.0f);
    const float mneg1 = -(g_norm[b * NSEQ + qb + r0 + (lane >> 2) + 8] + 2.0f);

    float l0 = 0.f, l1 = 0.f;
    float O[8][4];
    #pragma unroll
    for (int jc = 0; jc < 8; ++jc)
        #pragma unroll
        for (int q = 0; q < 4; ++q) O[jc][q] = 0.f;

    for (int blk = 0; blk < NBLK; ++blk) {
        const uint32_t XH = sb + XB_OFF + (blk & 1) * 32768u;
        const uint32_t XL = XH + 16384u;

        // issue next block's loads into the other buffer (prev compute synced)
        if (blk + 1 < NBLK) {
            const uint32_t NH = sb + XB_OFF + ((blk + 1) & 1) * 32768u;
            const size_t xrow = (size_t)(kh * KHALF + (blk + 1) * KB + tid) * CDIM;
            #pragma unroll
            for (int i = 0; i < 8; ++i) {
                cp16(swz(NH, tid, i * 16), xh + xrow + i * 8);
                cp16(swz(NH + 16384u, tid, i * 16), xl + xrow + i * 8);
            }
            CP_COMMIT();
            CP_WAIT(1);
        } else {
            CP_WAIT(0);
        }
        __syncthreads();

        // ---- GEMM1: S = Qh*Xh (f32 acc) + [Qh*Xl + Ql*Xh] (f16 acc) ----
        uint32_t aH[4][4], aL[4][4];
        {
            const int arow = r0 + (g & 1) * 8 + lr;
            const int acb  = (g >> 1) * 16;
            #pragma unroll
            for (int k = 0; k < 4; ++k) {
                ldsm4(swz(sb + QH_OFF, arow, k * 32 + acb), aH[k]);
                ldsm4(swz(sb + QL_OFF, arow, k * 32 + acb), aL[k]);
            }
        }
        float S[16][4];
        #pragma unroll
        for (int j = 0; j < 16; ++j) {
            const int krow = j * 8 + lr;
            uint32_t t0[4], t1[4], u0[4], u1[4];
            ldsm4(swz(XH, krow, g * 16), t0);
            ldsm4(swz(XH, krow, 64 + g * 16), t1);
            ldsm4(swz(XL, krow, g * 16), u0);
            ldsm4(swz(XL, krow, 64 + g * 16), u1);
            uint32_t bh[4][2] = {{t0[0],t0[1]},{t0[2],t0[3]},{t1[0],t1[1]},{t1[2],t1[3]}};
            uint32_t bl[4][2] = {{u0[0],u0[1]},{u0[2],u0[3]},{u1[0],u1[1]},{u1[2],u1[3]}};
            S[j][0] = 0.f; S[j][1] = 0.f; S[j][2] = 0.f; S[j][3] = 0.f;
            uint32_t Clo[2] = {0u, 0u};
            #pragma unroll
            for (int k = 0; k < 4; ++k) {
                mma16816(S[j], aH[k], bh[k]);
                mma16816h(Clo, aH[k], bl[k]);
                mma16816h(Clo, aL[k], bh[k]);
            }
            const float2 c01 = __half22float2(*(__half2*)&Clo[0]);
            const float2 c23 = __half22float2(*(__half2*)&Clo[1]);
            S[j][0] += c01.x; S[j][1] += c01.y;
            S[j][2] += c23.x; S[j][3] += c23.y;
        }

        // ---- static-max softmax: p = exp(S - M); no shuffles, no rescale ----
        uint32_t Ph[16][2];
        #pragma unroll
        for (int j = 0; j < 16; ++j) {
            float p0 = __expf(S[j][0] + mneg0), p1 = __expf(S[j][1] + mneg0);
            float p2 = __expf(S[j][2] + mneg1), p3 = __expf(S[j][3] + mneg1);
            l0 += p0 + p1; l1 += p2 + p3;
            __half2 H0 = __floats2half2_rn(p0, p1), H1 = __floats2half2_rn(p2, p3);
            Ph[j][0] = *(uint32_t*)&H0; Ph[j][1] = *(uint32_t*)&H1;
        }

        // ---- GEMM2: O[16 rows][64 ch] += Ph[16][128] * Vh[128][64] ----
        #pragma unroll
        for (int jc = 0; jc < 8; ++jc) {
            uint32_t vh[8][2];
            #pragma unroll
            for (int kp = 0; kp < 4; ++kp) {
                uint32_t t[4];
                const int key = kp * 32 + g * 8 + lr;
                ldsm4t(swz(XH, key, jc * 16), t);
                vh[2*kp][0] = t[0]; vh[2*kp][1] = t[1];
                vh[2*kp+1][0] = t[2]; vh[2*kp+1][1] = t[3];
            }
            #pragma unroll
            for (int kk = 0; kk < 8; ++kk) {
                uint32_t Ah[4] = {Ph[2*kk][0], Ph[2*kk][1], Ph[2*kk+1][0], Ph[2*kk+1][1]};
                mma16816(O[jc], Ah, vh[kk]);
            }
        }
        __syncthreads();   // all warps done with this buffer before it is overwritten
    }

    // ---- deferred l reduction (4 lanes share a row) + write partials ----
    l0 += __shfl_xor_sync(0xffffffffu, l0, 1);
    l0 += __shfl_xor_sync(0xffffffffu, l0, 2);
    l1 += __shfl_xor_sync(0xffffffffu, l1, 1);
    l1 += __shfl_xor_sync(0xffffffffu, l1, 2);

    const int ra = qb + r0 + (lane >> 2);
    const size_t pb = (size_t)(b * KSPLIT + kh) * NSEQ;
    if ((lane & 3) == 0) {
        g_lpart[pb + ra] = l0;
        g_lpart[pb + ra + 8] = l1;
    }
    #pragma unroll
    for (int jc = 0; jc < 8; ++jc) {
        const int ch = jc * 8 + 2 * (lane & 3);
        *(float2*)&g_Opart[(pb + ra) * CDIM + ch]     = make_float2(O[jc][0], O[jc][1]);
        *(float2*)&g_Opart[(pb + ra + 8) * CDIM + ch] = make_float2(O[jc][2], O[jc][3]);
    }
}

__global__ __launch_bounds__(256) void merge_kernel(const float* __restrict__ x,
                                                    const float* __restrict__ gamma,
                                                    float* __restrict__ out)
{
    const int i = blockIdx.x * 256 + threadIdx.x;      // 131072 float4s total
    const int c4 = i & 15;
    const int r  = (i >> 4) & (NSEQ - 1);
    const int b  = i >> 16;

    float den = 0.f;
    float4 acc = make_float4(0.f, 0.f, 0.f, 0.f);
    #pragma unroll
    for (int s = 0; s < KSPLIT; ++s) {
        const size_t p = (size_t)(b * KSPLIT + s) * NSEQ + r;
        den += g_lpart[p];
        const float4 o = ((const float4*)&g_Opart[p * CDIM])[c4];
        acc.x += o.x; acc.y += o.y; acc.z += o.z; acc.w += o.w;
    }
    const float4 xv = ((const float4*)&x[((size_t)b * NSEQ + r) * CDIM])[c4];
    const float gg = gamma[0], inv = 1.0f / den;
    float4 o;
    o.x = gg * acc.x * inv + xv.x;
    o.y = gg * acc.y * inv + xv.y;
    o.z = gg * acc.z * inv + xv.z;
    o.w = gg * acc.w * inv + xv.w;
    ((float4*)&out[((size_t)b * NSEQ + r) * CDIM])[c4] = o;
}

extern "C" void kernel_launch(void* const* d_in, const int* in_sizes, int n_in,
                              void* d_out, int out_size)
{
    const float* x     = (const float*)d_in[0];
    const float* gamma = (const float*)d_in[1];
    float* out = (float*)d_out;
    (void)in_sizes; (void)n_in; (void)out_size;

    cudaFuncSetAttribute(attn_main, cudaFuncAttributeMaxDynamicSharedMemorySize, SMEM_BYTES);
    split_kernel<<<512, 256>>>(x);
    attn_main<<<dim3(NSEQ / MT, 2, KSPLIT), 128, SMEM_BYTES>>>();
    merge_kernel<<<512, 256>>>(x, gamma, out);
}

// round 12
// speedup vs baseline: 1.1015x; 1.1015x over previous
#include <cuda_runtime.h>
#include <cuda_fp16.h>
#include <math.h>
#include <stdint.h>

#define NSEQ  4096
#define CDIM  64
#define MT    64
#define KB    128
#define KSPLIT 2
#define KHALF (NSEQ / KSPLIT)      // 2048
#define NBLK  (KHALF / KB)         // 16

// scratch (allocation-free rule -> __device__ globals)
__device__ __half g_xh[2 * NSEQ * CDIM];
__device__ __half g_xl[2 * NSEQ * CDIM];
__device__ float g_Opart[2 * KSPLIT * NSEQ * CDIM];
__device__ float g_lpart[2 * KSPLIT * NSEQ];
__device__ float g_mpart[2 * KSPLIT * NSEQ];

// smem layout (bytes): QH 64x128B; X double-buffered hi/lo 128x128B each
#define QH_OFF 0u
#define XB_OFF 8192u               // buf b at XB_OFF + b*32768 (hi), +16384 (lo)
#define SMEM_BYTES 73728u          // 72KB

__device__ __forceinline__ uint32_t cvta_smem(const void* p) {
    uint32_t a;
    asm("{ .reg .u64 t; cvta.to.shared.u64 t, %1; cvt.u32.u64 %0, t; }" : "=r"(a) : "l"(p));
    return a;
}
__device__ __forceinline__ void ldsm4(uint32_t addr, uint32_t* r) {
    asm volatile("ldmatrix.sync.aligned.m8n8.x4.shared.b16 {%0,%1,%2,%3}, [%4];"
                 : "=r"(r[0]), "=r"(r[1]), "=r"(r[2]), "=r"(r[3]) : "r"(addr));
}
__device__ __forceinline__ void ldsm4t(uint32_t addr, uint32_t* r) {
    asm volatile("ldmatrix.sync.aligned.m8n8.x4.trans.shared.b16 {%0,%1,%2,%3}, [%4];"
                 : "=r"(r[0]), "=r"(r[1]), "=r"(r[2]), "=r"(r[3]) : "r"(addr));
}
__device__ __forceinline__ void mma16816(float* c, const uint32_t* a, const uint32_t* b) {
    asm volatile("mma.sync.aligned.m16n8k16.row.col.f32.f16.f16.f32 "
                 "{%0,%1,%2,%3}, {%4,%5,%6,%7}, {%8,%9}, {%0,%1,%2,%3};"
                 : "+f"(c[0]), "+f"(c[1]), "+f"(c[2]), "+f"(c[3])
                 : "r"(a[0]), "r"(a[1]), "r"(a[2]), "r"(a[3]), "r"(b[0]), "r"(b[1]));
}
// fp16-accumulator variant for the small GEMM1 correction term
__device__ __forceinline__ void mma16816h(uint32_t* c, const uint32_t* a, const uint32_t* b) {
    asm volatile("mma.sync.aligned.m16n8k16.row.col.f16.f16.f16.f16 "
                 "{%0,%1}, {%2,%3,%4,%5}, {%6,%7}, {%0,%1};"
                 : "+r"(c[0]), "+r"(c[1])
                 : "r"(a[0]), "r"(a[1]), "r"(a[2]), "r"(a[3]), "r"(b[0]), "r"(b[1]));
}
__device__ __forceinline__ void cp16(uint32_t dst, const void* src) {
    asm volatile("cp.async.cg.shared.global [%0], [%1], 16;" :: "r"(dst), "l"(src));
}
#define CP_COMMIT()  asm volatile("cp.async.commit_group;" ::: "memory")
#define CP_WAIT(n)   asm volatile("cp.async.wait_group %0;" :: "n"(n) : "memory")

// XOR-swizzled byte offset inside a 128B-row tile
__device__ __forceinline__ uint32_t swz(uint32_t tb, int row, int cb) {
    return tb + row * 128 + (((((unsigned)cb >> 4) ^ (row & 7)) << 4) | (cb & 15));
}

// ---- pre-pass: split fp32 x into fp16 hi + lo ----
__global__ __launch_bounds__(256) void split_kernel(const float* __restrict__ x)
{
    const int i = blockIdx.x * 256 + threadIdx.x;   // 131072 float4s
    float4 v = ((const float4*)x)[i];
    __half h0 = __float2half_rn(v.x), h1 = __float2half_rn(v.y);
    __half h2 = __float2half_rn(v.z), h3 = __float2half_rn(v.w);
    __half2 H0 = __halves2half2(h0, h1), H1 = __halves2half2(h2, h3);
    __half2 L0 = __floats2half2_rn(v.x - __half2float(h0), v.y - __half2float(h1));
    __half2 L1 = __floats2half2_rn(v.z - __half2float(h2), v.w - __half2float(h3));
    ((uint2*)g_xh)[i] = make_uint2(*(uint32_t*)&H0, *(uint32_t*)&H1);
    ((uint2*)g_xl)[i] = make_uint2(*(uint32_t*)&L0, *(uint32_t*)&L1);
}

__global__ __launch_bounds__(128, 2) void attn_main()
{
    extern __shared__ char sm[];
    const uint32_t sb = cvta_smem(sm);
    const int tid = threadIdx.x, lane = tid & 31, w = tid >> 5;
    const int qb = blockIdx.x * MT, b = blockIdx.y, kh = blockIdx.z;
    const __half* xh = g_xh + (size_t)b * NSEQ * CDIM;
    const __half* xl = g_xl + (size_t)b * NSEQ * CDIM;

    // prologue: Q hi + X block 0 via cp.async (one group)
    {
        const int row = tid >> 1, h = tid & 1;
        #pragma unroll
        for (int i = 0; i < 4; ++i) {
            const int cb = h * 64 + i * 16;     // byte col within 128B row
            cp16(swz(sb + QH_OFF, row, cb), xh + (size_t)(qb + row) * CDIM + h * 32 + i * 8);
        }
        const size_t xrow = (size_t)(kh * KHALF + tid) * CDIM;
        #pragma unroll
        for (int i = 0; i < 8; ++i) {
            cp16(swz(sb + XB_OFF, tid, i * 16), xh + xrow + i * 8);
            cp16(swz(sb + XB_OFF + 16384u, tid, i * 16), xl + xrow + i * 8);
        }
        CP_COMMIT();
    }
    CP_WAIT(0);
    __syncthreads();

    const int r0 = w * 16;
    const int g = lane >> 3, lr = lane & 7;

    // ---- hoisted Q-hi fragments (loop-invariant; QH never overwritten) ----
    uint32_t aH[4][4];
    {
        const int arow = r0 + (g & 1) * 8 + lr;
        const int acb  = (g >> 1) * 16;
        #pragma unroll
        for (int k = 0; k < 4; ++k)
            ldsm4(swz(sb + QH_OFF, arow, k * 32 + acb), aH[k]);
    }

    float m0 = -1e30f, m1 = -1e30f, l0 = 0.f, l1 = 0.f;
    float O[8][4];
    #pragma unroll
    for (int jc = 0; jc < 8; ++jc)
        #pragma unroll
        for (int q = 0; q < 4; ++q) O[jc][q] = 0.f;

    for (int blk = 0; blk < NBLK; ++blk) {
        const uint32_t XH = sb + XB_OFF + (blk & 1) * 32768u;
        const uint32_t XL = XH + 16384u;

        // issue next block's loads into the other buffer
        if (blk + 1 < NBLK) {
            const uint32_t NH = sb + XB_OFF + ((blk + 1) & 1) * 32768u;
            const size_t xrow = (size_t)(kh * KHALF + (blk + 1) * KB + tid) * CDIM;
            #pragma unroll
            for (int i = 0; i < 8; ++i) {
                cp16(swz(NH, tid, i * 16), xh + xrow + i * 8);
                cp16(swz(NH + 16384u, tid, i * 16), xl + xrow + i * 8);
            }
            CP_COMMIT();
            CP_WAIT(1);
        } else {
            CP_WAIT(0);
        }
        __syncthreads();

        // ---- GEMM1: S = Qh*Xh (f32 acc) + Qh*Xl (f16 acc) == Qh * X exactly ----
        float S[16][4];
        #pragma unroll
        for (int j = 0; j < 16; ++j) {
            const int krow = j * 8 + lr;
            uint32_t t0[4], t1[4], u0[4], u1[4];
            ldsm4(swz(XH, krow, g * 16), t0);
            ldsm4(swz(XH, krow, 64 + g * 16), t1);
            ldsm4(swz(XL, krow, g * 16), u0);
            ldsm4(swz(XL, krow, 64 + g * 16), u1);
            uint32_t bh[4][2] = {{t0[0],t0[1]},{t0[2],t0[3]},{t1[0],t1[1]},{t1[2],t1[3]}};
            uint32_t bl[4][2] = {{u0[0],u0[1]},{u0[2],u0[3]},{u1[0],u1[1]},{u1[2],u1[3]}};
            S[j][0] = 0.f; S[j][1] = 0.f; S[j][2] = 0.f; S[j][3] = 0.f;
            uint32_t Clo[2] = {0u, 0u};
            #pragma unroll
            for (int k = 0; k < 4; ++k) {
                mma16816(S[j], aH[k], bh[k]);
                mma16816h(Clo, aH[k], bl[k]);
            }
            const float2 c01 = __half22float2(*(__half2*)&Clo[0]);
            const float2 c23 = __half22float2(*(__half2*)&Clo[1]);
            S[j][0] += c01.x; S[j][1] += c01.y;
            S[j][2] += c23.x; S[j][3] += c23.y;
        }

        // ---- online softmax (rows: ra = lane/4, rb = ra+8) ----
        float mx0 = -1e30f, mx1 = -1e30f;
        #pragma unroll
        for (int j = 0; j < 16; ++j) {
            mx0 = fmaxf(mx0, fmaxf(S[j][0], S[j][1]));
            mx1 = fmaxf(mx1, fmaxf(S[j][2], S[j][3]));
        }
        mx0 = fmaxf(mx0, __shfl_xor_sync(0xffffffffu, mx0, 1));
        mx0 = fmaxf(mx0, __shfl_xor_sync(0xffffffffu, mx0, 2));
        mx1 = fmaxf(mx1, __shfl_xor_sync(0xffffffffu, mx1, 1));
        mx1 = fmaxf(mx1, __shfl_xor_sync(0xffffffffu, mx1, 2));
        const float mn0 = fmaxf(m0, mx0), mn1 = fmaxf(m1, mx1);
        const float cr0 = __expf(m0 - mn0), cr1 = __expf(m1 - mn1);
        m0 = mn0; m1 = mn1;

        float s0 = 0.f, s1 = 0.f;
        uint32_t Ph[16][2];
        #pragma unroll
        for (int j = 0; j < 16; ++j) {
            float p0 = __expf(S[j][0] - mn0), p1 = __expf(S[j][1] - mn0);
            float p2 = __expf(S[j][2] - mn1), p3 = __expf(S[j][3] - mn1);
            s0 += p0 + p1; s1 += p2 + p3;
            __half2 H0 = __floats2half2_rn(p0, p1), H1 = __floats2half2_rn(p2, p3);
            Ph[j][0] = *(uint32_t*)&H0; Ph[j][1] = *(uint32_t*)&H1;
        }
        s0 += __shfl_xor_sync(0xffffffffu, s0, 1);
        s0 += __shfl_xor_sync(0xffffffffu, s0, 2);
        s1 += __shfl_xor_sync(0xffffffffu, s1, 1);
        s1 += __shfl_xor_sync(0xffffffffu, s1, 2);
        l0 = l0 * cr0 + s0; l1 = l1 * cr1 + s1;
        #pragma unroll
        for (int jc = 0; jc < 8; ++jc) {
            O[jc][0] *= cr0; O[jc][1] *= cr0; O[jc][2] *= cr1; O[jc][3] *= cr1;
        }

        // ---- GEMM2: O[16 rows][64 ch] += Ph[16][128] * Vh[128][64] ----
        #pragma unroll
        for (int jc = 0; jc < 8; ++jc) {
            uint32_t vh[8][2];
            #pragma unroll
            for (int kp = 0; kp < 4; ++kp) {
                uint32_t t[4];
                const int key = kp * 32 + g * 8 + lr;
                ldsm4t(swz(XH, key, jc * 16), t);
                vh[2*kp][0] = t[0]; vh[2*kp][1] = t[1];
                vh[2*kp+1][0] = t[2]; vh[2*kp+1][1] = t[3];
            }
            #pragma unroll
            for (int kk = 0; kk < 8; ++kk) {
                uint32_t Ah[4] = {Ph[2*kk][0], Ph[2*kk][1], Ph[2*kk+1][0], Ph[2*kk+1][1]};
                mma16816(O[jc], Ah, vh[kk]);
            }
        }
        __syncthreads();   // all warps done with this buffer before it is overwritten
    }

    // ---- write per-half partials ----
    const int ra = qb + r0 + (lane >> 2);
    const size_t pb = (size_t)(b * KSPLIT + kh) * NSEQ;
    if ((lane & 3) == 0) {
        g_mpart[pb + ra] = m0;     g_lpart[pb + ra] = l0;
        g_mpart[pb + ra + 8] = m1; g_lpart[pb + ra + 8] = l1;
    }
    #pragma unroll
    for (int jc = 0; jc < 8; ++jc) {
        const int ch = jc * 8 + 2 * (lane & 3);
        *(float2*)&g_Opart[(pb + ra) * CDIM + ch]     = make_float2(O[jc][0], O[jc][1]);
        *(float2*)&g_Opart[(pb + ra + 8) * CDIM + ch] = make_float2(O[jc][2], O[jc][3]);
    }
}

__global__ __launch_bounds__(256) void merge_kernel(const float* __restrict__ x,
                                                    const float* __restrict__ gamma,
                                                    float* __restrict__ out)
{
    const int i = blockIdx.x * 256 + threadIdx.x;      // 131072 float4s total
    const int c4 = i & 15;
    const int r  = (i >> 4) & (NSEQ - 1);
    const int b  = i >> 16;
    const size_t p0 = (size_t)(b * KSPLIT) * NSEQ + r, p1 = p0 + NSEQ;
    const float M  = fmaxf(g_mpart[p0], g_mpart[p1]);
    const float w0 = __expf(g_mpart[p0] - M), w1 = __expf(g_mpart[p1] - M);
    const float inv = 1.0f / (w0 * g_lpart[p0] + w1 * g_lpart[p1]);
    const float4 o0 = ((const float4*)&g_Opart[p0 * CDIM])[c4];
    const float4 o1 = ((const float4*)&g_Opart[p1 * CDIM])[c4];
    const float4 xv = ((const float4*)&x[((size_t)b * NSEQ + r) * CDIM])[c4];
    const float gg = gamma[0];
    float4 o;
    o.x = gg * (w0 * o0.x + w1 * o1.x) * inv + xv.x;
    o.y = gg * (w0 * o0.y + w1 * o1.y) * inv + xv.y;
    o.z = gg * (w0 * o0.z + w1 * o1.z) * inv + xv.z;
    o.w = gg * (w0 * o0.w + w1 * o1.w) * inv + xv.w;
    ((float4*)&out[((size_t)b * NSEQ + r) * CDIM])[c4] = o;
}

extern "C" void kernel_launch(void* const* d_in, const int* in_sizes, int n_in,
                              void* d_out, int out_size)
{
    const float* x     = (const float*)d_in[0];
    const float* gamma = (const float*)d_in[1];
    float* out = (float*)d_out;
    (void)in_sizes; (void)n_in; (void)out_size;

    cudaFuncSetAttribute(attn_main, cudaFuncAttributeMaxDynamicSharedMemorySize, SMEM_BYTES);
    split_kernel<<<512, 256>>>(x);
    attn_main<<<dim3(NSEQ / MT, 2, KSPLIT), 128, SMEM_BYTES>>>();
    merge_kernel<<<512, 256>>>(x, gamma, out);
}

// round 13
// speedup vs baseline: 1.2139x; 1.1020x over previous
#include <cuda_runtime.h>
#include <cuda_fp16.h>
#include <math.h>
#include <stdint.h>

#define NSEQ  4096
#define CDIM  64
#define MT    64
#define KB    128
#define KSPLIT 8
#define KHALF (NSEQ / KSPLIT)      // 512
#define NBLK  (KHALF / KB)         // 4

// scratch (allocation-free rule -> __device__ globals)
__device__ __half g_xh[2 * NSEQ * CDIM];
__device__ __half g_xl[2 * NSEQ * CDIM];
__device__ float g_Opart[2 * KSPLIT * NSEQ * CDIM];
__device__ float g_lpart[2 * KSPLIT * NSEQ];
__device__ float g_mpart[2 * KSPLIT * NSEQ];

// smem layout (bytes): QH 64x128B; X double-buffered hi/lo 128x128B each
#define QH_OFF 0u
#define XB_OFF 8192u               // buf b at XB_OFF + b*32768 (hi), +16384 (lo)
#define SMEM_BYTES 73728u          // 72KB -> 3 CTAs/SM

__device__ __forceinline__ uint32_t cvta_smem(const void* p) {
    uint32_t a;
    asm("{ .reg .u64 t; cvta.to.shared.u64 t, %1; cvt.u32.u64 %0, t; }" : "=r"(a) : "l"(p));
    return a;
}
__device__ __forceinline__ void ldsm4(uint32_t addr, uint32_t* r) {
    asm volatile("ldmatrix.sync.aligned.m8n8.x4.shared.b16 {%0,%1,%2,%3}, [%4];"
                 : "=r"(r[0]), "=r"(r[1]), "=r"(r[2]), "=r"(r[3]) : "r"(addr));
}
__device__ __forceinline__ void ldsm4t(uint32_t addr, uint32_t* r) {
    asm volatile("ldmatrix.sync.aligned.m8n8.x4.trans.shared.b16 {%0,%1,%2,%3}, [%4];"
                 : "=r"(r[0]), "=r"(r[1]), "=r"(r[2]), "=r"(r[3]) : "r"(addr));
}
__device__ __forceinline__ void mma16816(float* c, const uint32_t* a, const uint32_t* b) {
    asm volatile("mma.sync.aligned.m16n8k16.row.col.f32.f16.f16.f32 "
                 "{%0,%1,%2,%3}, {%4,%5,%6,%7}, {%8,%9}, {%0,%1,%2,%3};"
                 : "+f"(c[0]), "+f"(c[1]), "+f"(c[2]), "+f"(c[3])
                 : "r"(a[0]), "r"(a[1]), "r"(a[2]), "r"(a[3]), "r"(b[0]), "r"(b[1]));
}
// fp16-accumulator variant for the small GEMM1 correction term
__device__ __forceinline__ void mma16816h(uint32_t* c, const uint32_t* a, const uint32_t* b) {
    asm volatile("mma.sync.aligned.m16n8k16.row.col.f16.f16.f16.f16 "
                 "{%0,%1}, {%2,%3,%4,%5}, {%6,%7}, {%0,%1};"
                 : "+r"(c[0]), "+r"(c[1])
                 : "r"(a[0]), "r"(a[1]), "r"(a[2]), "r"(a[3]), "r"(b[0]), "r"(b[1]));
}
__device__ __forceinline__ void cp16(uint32_t dst, const void* src) {
    asm volatile("cp.async.cg.shared.global [%0], [%1], 16;" :: "r"(dst), "l"(src));
}
#define CP_COMMIT()  asm volatile("cp.async.commit_group;" ::: "memory")
#define CP_WAIT(n)   asm volatile("cp.async.wait_group %0;" :: "n"(n) : "memory")

// XOR-swizzled byte offset inside a 128B-row tile
__device__ __forceinline__ uint32_t swz(uint32_t tb, int row, int cb) {
    return tb + row * 128 + (((((unsigned)cb >> 4) ^ (row & 7)) << 4) | (cb & 15));
}

// ---- pre-pass: split fp32 x into fp16 hi + lo ----
__global__ __launch_bounds__(256) void split_kernel(const float* __restrict__ x)
{
    const int i = blockIdx.x * 256 + threadIdx.x;   // 131072 float4s
    float4 v = ((const float4*)x)[i];
    __half h0 = __float2half_rn(v.x), h1 = __float2half_rn(v.y);
    __half h2 = __float2half_rn(v.z), h3 = __float2half_rn(v.w);
    __half2 H0 = __halves2half2(h0, h1), H1 = __halves2half2(h2, h3);
    __half2 L0 = __floats2half2_rn(v.x - __half2float(h0), v.y - __half2float(h1));
    __half2 L1 = __floats2half2_rn(v.z - __half2float(h2), v.w - __half2float(h3));
    ((uint2*)g_xh)[i] = make_uint2(*(uint32_t*)&H0, *(uint32_t*)&H1);
    ((uint2*)g_xl)[i] = make_uint2(*(uint32_t*)&L0, *(uint32_t*)&L1);
}

__global__ __launch_bounds__(128, 3) void attn_main()
{
    extern __shared__ char sm[];
    const uint32_t sb = cvta_smem(sm);
    const int tid = threadIdx.x, lane = tid & 31, w = tid >> 5;
    const int qb = blockIdx.x * MT, b = blockIdx.y, kh = blockIdx.z;
    const __half* xh = g_xh + (size_t)b * NSEQ * CDIM;
    const __half* xl = g_xl + (size_t)b * NSEQ * CDIM;

    // prologue: Q hi + X block 0 via cp.async (one group)
    {
        const int row = tid >> 1, h = tid & 1;
        #pragma unroll
        for (int i = 0; i < 4; ++i) {
            const int cb = h * 64 + i * 16;     // byte col within 128B row
            cp16(swz(sb + QH_OFF, row, cb), xh + (size_t)(qb + row) * CDIM + h * 32 + i * 8);
        }
        const size_t xrow = (size_t)(kh * KHALF + tid) * CDIM;
        #pragma unroll
        for (int i = 0; i < 8; ++i) {
            cp16(swz(sb + XB_OFF, tid, i * 16), xh + xrow + i * 8);
            cp16(swz(sb + XB_OFF + 16384u, tid, i * 16), xl + xrow + i * 8);
        }
        CP_COMMIT();
    }
    CP_WAIT(0);
    __syncthreads();

    const int r0 = w * 16;
    const int g = lane >> 3, lr = lane & 7;

    // ---- hoisted Q-hi fragments (loop-invariant; QH never overwritten) ----
    uint32_t aH[4][4];
    {
        const int arow = r0 + (g & 1) * 8 + lr;
        const int acb  = (g >> 1) * 16;
        #pragma unroll
        for (int k = 0; k < 4; ++k)
            ldsm4(swz(sb + QH_OFF, arow, k * 32 + acb), aH[k]);
    }

    float m0 = -1e30f, m1 = -1e30f, l0 = 0.f, l1 = 0.f;
    float O[8][4];
    #pragma unroll
    for (int jc = 0; jc < 8; ++jc)
        #pragma unroll
        for (int q = 0; q < 4; ++q) O[jc][q] = 0.f;

    for (int blk = 0; blk < NBLK; ++blk) {
        const uint32_t XH = sb + XB_OFF + (blk & 1) * 32768u;
        const uint32_t XL = XH + 16384u;

        // issue next block's loads into the other buffer
        if (blk + 1 < NBLK) {
            const uint32_t NH = sb + XB_OFF + ((blk + 1) & 1) * 32768u;
            const size_t xrow = (size_t)(kh * KHALF + (blk + 1) * KB + tid) * CDIM;
            #pragma unroll
            for (int i = 0; i < 8; ++i) {
                cp16(swz(NH, tid, i * 16), xh + xrow + i * 8);
                cp16(swz(NH + 16384u, tid, i * 16), xl + xrow + i * 8);
            }
            CP_COMMIT();
            CP_WAIT(1);
        } else {
            CP_WAIT(0);
        }
        __syncthreads();

        // ---- GEMM1: S = Qh*Xh (f32 acc) + Qh*Xl (f16 acc) == Qh * X exactly ----
        float S[16][4];
        #pragma unroll
        for (int j = 0; j < 16; ++j) {
            const int krow = j * 8 + lr;
            uint32_t t0[4], t1[4], u0[4], u1[4];
            ldsm4(swz(XH, krow, g * 16), t0);
            ldsm4(swz(XH, krow, 64 + g * 16), t1);
            ldsm4(swz(XL, krow, g * 16), u0);
            ldsm4(swz(XL, krow, 64 + g * 16), u1);
            uint32_t bh[4][2] = {{t0[0],t0[1]},{t0[2],t0[3]},{t1[0],t1[1]},{t1[2],t1[3]}};
            uint32_t bl[4][2] = {{u0[0],u0[1]},{u0[2],u0[3]},{u1[0],u1[1]},{u1[2],u1[3]}};
            S[j][0] = 0.f; S[j][1] = 0.f; S[j][2] = 0.f; S[j][3] = 0.f;
            uint32_t Clo[2] = {0u, 0u};
            #pragma unroll
            for (int k = 0; k < 4; ++k) {
                mma16816(S[j], aH[k], bh[k]);
                mma16816h(Clo, aH[k], bl[k]);
            }
            const float2 c01 = __half22float2(*(__half2*)&Clo[0]);
            const float2 c23 = __half22float2(*(__half2*)&Clo[1]);
            S[j][0] += c01.x; S[j][1] += c01.y;
            S[j][2] += c23.x; S[j][3] += c23.y;
        }

        // ---- online softmax (rows: ra = lane/4, rb = ra+8) ----
        float mx0 = -1e30f, mx1 = -1e30f;
        #pragma unroll
        for (int j = 0; j < 16; ++j) {
            mx0 = fmaxf(mx0, fmaxf(S[j][0], S[j][1]));
            mx1 = fmaxf(mx1, fmaxf(S[j][2], S[j][3]));
        }
        mx0 = fmaxf(mx0, __shfl_xor_sync(0xffffffffu, mx0, 1));
        mx0 = fmaxf(mx0, __shfl_xor_sync(0xffffffffu, mx0, 2));
        mx1 = fmaxf(mx1, __shfl_xor_sync(0xffffffffu, mx1, 1));
        mx1 = fmaxf(mx1, __shfl_xor_sync(0xffffffffu, mx1, 2));
        const float mn0 = fmaxf(m0, mx0), mn1 = fmaxf(m1, mx1);
        const float cr0 = __expf(m0 - mn0), cr1 = __expf(m1 - mn1);
        m0 = mn0; m1 = mn1;

        float s0 = 0.f, s1 = 0.f;
        uint32_t Ph[16][2];
        #pragma unroll
        for (int j = 0; j < 16; ++j) {
            float p0 = __expf(S[j][0] - mn0), p1 = __expf(S[j][1] - mn0);
            float p2 = __expf(S[j][2] - mn1), p3 = __expf(S[j][3] - mn1);
            s0 += p0 + p1; s1 += p2 + p3;
            __half2 H0 = __floats2half2_rn(p0, p1), H1 = __floats2half2_rn(p2, p3);
            Ph[j][0] = *(uint32_t*)&H0; Ph[j][1] = *(uint32_t*)&H1;
        }
        s0 += __shfl_xor_sync(0xffffffffu, s0, 1);
        s0 += __shfl_xor_sync(0xffffffffu, s0, 2);
        s1 += __shfl_xor_sync(0xffffffffu, s1, 1);
        s1 += __shfl_xor_sync(0xffffffffu, s1, 2);
        l0 = l0 * cr0 + s0; l1 = l1 * cr1 + s1;
        #pragma unroll
        for (int jc = 0; jc < 8; ++jc) {
            O[jc][0] *= cr0; O[jc][1] *= cr0; O[jc][2] *= cr1; O[jc][3] *= cr1;
        }

        // ---- GEMM2: O[16 rows][64 ch] += Ph[16][128] * Vh[128][64] ----
        #pragma unroll
        for (int jc = 0; jc < 8; ++jc) {
            uint32_t vh[8][2];
            #pragma unroll
            for (int kp = 0; kp < 4; ++kp) {
                uint32_t t[4];
                const int key = kp * 32 + g * 8 + lr;
                ldsm4t(swz(XH, key, jc * 16), t);
                vh[2*kp][0] = t[0]; vh[2*kp][1] = t[1];
                vh[2*kp+1][0] = t[2]; vh[2*kp+1][1] = t[3];
            }
            #pragma unroll
            for (int kk = 0; kk < 8; ++kk) {
                uint32_t Ah[4] = {Ph[2*kk][0], Ph[2*kk][1], Ph[2*kk+1][0], Ph[2*kk+1][1]};
                mma16816(O[jc], Ah, vh[kk]);
            }
        }
        __syncthreads();   // all warps done with this buffer before it is overwritten
    }

    // ---- write per-split partials ----
    const int ra = qb + r0 + (lane >> 2);
    const size_t pb = (size_t)(b * KSPLIT + kh) * NSEQ;
    if ((lane & 3) == 0) {
        g_mpart[pb + ra] = m0;     g_lpart[pb + ra] = l0;
        g_mpart[pb + ra + 8] = m1; g_lpart[pb + ra + 8] = l1;
    }
    #pragma unroll
    for (int jc = 0; jc < 8; ++jc) {
        const int ch = jc * 8 + 2 * (lane & 3);
        *(float2*)&g_Opart[(pb + ra) * CDIM + ch]     = make_float2(O[jc][0], O[jc][1]);
        *(float2*)&g_Opart[(pb + ra + 8) * CDIM + ch] = make_float2(O[jc][2], O[jc][3]);
    }
}

__global__ __launch_bounds__(256) void merge_kernel(const float* __restrict__ x,
                                                    const float* __restrict__ gamma,
                                                    float* __restrict__ out)
{
    const int i = blockIdx.x * 256 + threadIdx.x;      // 131072 float4s total
    const int c4 = i & 15;
    const int r  = (i >> 4) & (NSEQ - 1);
    const int b  = i >> 16;

    float mv[KSPLIT];
    float M = -1e30f;
    #pragma unroll
    for (int s = 0; s < KSPLIT; ++s) {
        mv[s] = g_mpart[(size_t)(b * KSPLIT + s) * NSEQ + r];
        M = fmaxf(M, mv[s]);
    }
    float den = 0.f;
    float4 acc = make_float4(0.f, 0.f, 0.f, 0.f);
    #pragma unroll
    for (int s = 0; s < KSPLIT; ++s) {
        const size_t p = (size_t)(b * KSPLIT + s) * NSEQ + r;
        const float ws = __expf(mv[s] - M);
        den += ws * g_lpart[p];
        const float4 o = ((const float4*)&g_Opart[p * CDIM])[c4];
        acc.x += ws * o.x; acc.y += ws * o.y; acc.z += ws * o.z; acc.w += ws * o.w;
    }
    const float4 xv = ((const float4*)&x[((size_t)b * NSEQ + r) * CDIM])[c4];
    const float gg = gamma[0], inv = 1.0f / den;
    float4 o;
    o.x = gg * acc.x * inv + xv.x;
    o.y = gg * acc.y * inv + xv.y;
    o.z = gg * acc.z * inv + xv.z;
    o.w = gg * acc.w * inv + xv.w;
    ((float4*)&out[((size_t)b * NSEQ + r) * CDIM])[c4] = o;
}

extern "C" void kernel_launch(void* const* d_in, const int* in_sizes, int n_in,
                              void* d_out, int out_size)
{
    const float* x     = (const float*)d_in[0];
    const float* gamma = (const float*)d_in[1];
    float* out = (float*)d_out;
    (void)in_sizes; (void)n_in; (void)out_size;

    cudaFuncSetAttribute(attn_main, cudaFuncAttributeMaxDynamicSharedMemorySize, SMEM_BYTES);
    split_kernel<<<512, 256>>>(x);
    attn_main<<<dim3(NSEQ / MT, 2, KSPLIT), 128, SMEM_BYTES>>>();
    merge_kernel<<<512, 256>>>(x, gamma, out);
}

// round 14
// speedup vs baseline: 1.5800x; 1.3016x over previous
#include <cuda_runtime.h>
#include <cuda_fp16.h>
#include <math.h>
#include <stdint.h>

#define NSEQ  4096
#define CDIM  64
#define MT    64
#define KB    64
#define KSPLIT 8
#define KHALF (NSEQ / KSPLIT)      // 512
#define NBLK  (KHALF / KB)         // 8

// scratch (allocation-free rule -> __device__ globals)
__device__ __half g_xh[2 * NSEQ * CDIM];
__device__ __half g_xl[2 * NSEQ * CDIM];
__device__ __half g_Opart[2 * KSPLIT * NSEQ * CDIM];
__device__ float  g_lpart[2 * KSPLIT * NSEQ];
__device__ float  g_mpart[2 * KSPLIT * NSEQ];

// smem layout (bytes): QH 64x128B (8KB); X double-buffered 64x128B hi+lo (16KB per buf)
#define QH_OFF 0u
#define XB_OFF 8192u               // buf b at XB_OFF + b*16384 (hi), +8192 (lo)
#define SMEM_BYTES 40960u          // 40KB -> 4 CTAs/SM

__device__ __forceinline__ uint32_t cvta_smem(const void* p) {
    uint32_t a;
    asm("{ .reg .u64 t; cvta.to.shared.u64 t, %1; cvt.u32.u64 %0, t; }" : "=r"(a) : "l"(p));
    return a;
}
__device__ __forceinline__ void ldsm4(uint32_t addr, uint32_t* r) {
    asm volatile("ldmatrix.sync.aligned.m8n8.x4.shared.b16 {%0,%1,%2,%3}, [%4];"
                 : "=r"(r[0]), "=r"(r[1]), "=r"(r[2]), "=r"(r[3]) : "r"(addr));
}
__device__ __forceinline__ void ldsm4t(uint32_t addr, uint32_t* r) {
    asm volatile("ldmatrix.sync.aligned.m8n8.x4.trans.shared.b16 {%0,%1,%2,%3}, [%4];"
                 : "=r"(r[0]), "=r"(r[1]), "=r"(r[2]), "=r"(r[3]) : "r"(addr));
}
__device__ __forceinline__ void mma16816(float* c, const uint32_t* a, const uint32_t* b) {
    asm volatile("mma.sync.aligned.m16n8k16.row.col.f32.f16.f16.f32 "
                 "{%0,%1,%2,%3}, {%4,%5,%6,%7}, {%8,%9}, {%0,%1,%2,%3};"
                 : "+f"(c[0]), "+f"(c[1]), "+f"(c[2]), "+f"(c[3])
                 : "r"(a[0]), "r"(a[1]), "r"(a[2]), "r"(a[3]), "r"(b[0]), "r"(b[1]));
}
// fp16-accumulator variant for the small GEMM1 correction term
__device__ __forceinline__ void mma16816h(uint32_t* c, const uint32_t* a, const uint32_t* b) {
    asm volatile("mma.sync.aligned.m16n8k16.row.col.f16.f16.f16.f16 "
                 "{%0,%1}, {%2,%3,%4,%5}, {%6,%7}, {%0,%1};"
                 : "+r"(c[0]), "+r"(c[1])
                 : "r"(a[0]), "r"(a[1]), "r"(a[2]), "r"(a[3]), "r"(b[0]), "r"(b[1]));
}
__device__ __forceinline__ void cp16(uint32_t dst, const void* src) {
    asm volatile("cp.async.cg.shared.global [%0], [%1], 16;" :: "r"(dst), "l"(src));
}
#define CP_COMMIT()  asm volatile("cp.async.commit_group;" ::: "memory")
#define CP_WAIT(n)   asm volatile("cp.async.wait_group %0;" :: "n"(n) : "memory")

// XOR-swizzled byte offset inside a 128B-row tile
__device__ __forceinline__ uint32_t swz(uint32_t tb, int row, int cb) {
    return tb + row * 128 + (((((unsigned)cb >> 4) ^ (row & 7)) << 4) | (cb & 15));
}

// ---- pre-pass: split fp32 x into fp16 hi + lo ----
__global__ __launch_bounds__(256) void split_kernel(const float* __restrict__ x)
{
    const int i = blockIdx.x * 256 + threadIdx.x;   // 131072 float4s
    float4 v = ((const float4*)x)[i];
    __half h0 = __float2half_rn(v.x), h1 = __float2half_rn(v.y);
    __half h2 = __float2half_rn(v.z), h3 = __float2half_rn(v.w);
    __half2 H0 = __halves2half2(h0, h1), H1 = __halves2half2(h2, h3);
    __half2 L0 = __floats2half2_rn(v.x - __half2float(h0), v.y - __half2float(h1));
    __half2 L1 = __floats2half2_rn(v.z - __half2float(h2), v.w - __half2float(h3));
    ((uint2*)g_xh)[i] = make_uint2(*(uint32_t*)&H0, *(uint32_t*)&H1);
    ((uint2*)g_xl)[i] = make_uint2(*(uint32_t*)&L0, *(uint32_t*)&L1);
}

__global__ __launch_bounds__(128, 4) void attn_main()
{
    extern __shared__ char sm[];
    const uint32_t sb = cvta_smem(sm);
    const int tid = threadIdx.x, lane = tid & 31, w = tid >> 5;
    const int qb = blockIdx.x * MT, b = blockIdx.y, kh = blockIdx.z;
    const __half* xh = g_xh + (size_t)b * NSEQ * CDIM;
    const __half* xl = g_xl + (size_t)b * NSEQ * CDIM;

    // prologue: Q hi + X block 0 via cp.async (one group)
    {
        const int row = tid >> 1, h = tid & 1;
        #pragma unroll
        for (int i = 0; i < 4; ++i) {
            const int cb = h * 64 + i * 16;     // byte col within 128B row
            cp16(swz(sb + QH_OFF, row, cb), xh + (size_t)(qb + row) * CDIM + h * 32 + i * 8);
        }
        const size_t xrow = (size_t)(kh * KHALF + row) * CDIM + h * 32;
        #pragma unroll
        for (int i = 0; i < 4; ++i) {
            const int cb = h * 64 + i * 16;
            cp16(swz(sb + XB_OFF, row, cb), xh + xrow + i * 8);
            cp16(swz(sb + XB_OFF + 8192u, row, cb), xl + xrow + i * 8);
        }
        CP_COMMIT();
    }
    CP_WAIT(0);
    __syncthreads();

    const int r0 = w * 16;
    const int g = lane >> 3, lr = lane & 7;

    // ---- hoisted Q-hi fragments (loop-invariant; QH never overwritten) ----
    uint32_t aH[4][4];
    {
        const int arow = r0 + (g & 1) * 8 + lr;
        const int acb  = (g >> 1) * 16;
        #pragma unroll
        for (int k = 0; k < 4; ++k)
            ldsm4(swz(sb + QH_OFF, arow, k * 32 + acb), aH[k]);
    }

    float m0 = -1e30f, m1 = -1e30f, l0 = 0.f, l1 = 0.f;
    float O[8][4];
    #pragma unroll
    for (int jc = 0; jc < 8; ++jc)
        #pragma unroll
        for (int q = 0; q < 4; ++q) O[jc][q] = 0.f;

    for (int blk = 0; blk < NBLK; ++blk) {
        const uint32_t XH = sb + XB_OFF + (blk & 1) * 16384u;
        const uint32_t XL = XH + 8192u;

        // issue next block's loads into the other buffer
        if (blk + 1 < NBLK) {
            const uint32_t NH = sb + XB_OFF + ((blk + 1) & 1) * 16384u;
            const int row = tid >> 1, h = tid & 1;
            const size_t xrow = (size_t)(kh * KHALF + (blk + 1) * KB + row) * CDIM + h * 32;
            #pragma unroll
            for (int i = 0; i < 4; ++i) {
                const int cb = h * 64 + i * 16;
                cp16(swz(NH, row, cb), xh + xrow + i * 8);
                cp16(swz(NH + 8192u, row, cb), xl + xrow + i * 8);
            }
            CP_COMMIT();
            CP_WAIT(1);
        } else {
            CP_WAIT(0);
        }
        __syncthreads();

        // ---- GEMM1: S = Qh*Xh (f32 acc) + Qh*Xl (f16 acc) == Qh * X exactly ----
        float S[8][4];
        #pragma unroll
        for (int j = 0; j < 8; ++j) {
            const int krow = j * 8 + lr;
            uint32_t t0[4], t1[4], u0[4], u1[4];
            ldsm4(swz(XH, krow, g * 16), t0);
            ldsm4(swz(XH, krow, 64 + g * 16), t1);
            ldsm4(swz(XL, krow, g * 16), u0);
            ldsm4(swz(XL, krow, 64 + g * 16), u1);
            uint32_t bh[4][2] = {{t0[0],t0[1]},{t0[2],t0[3]},{t1[0],t1[1]},{t1[2],t1[3]}};
            uint32_t bl[4][2] = {{u0[0],u0[1]},{u0[2],u0[3]},{u1[0],u1[1]},{u1[2],u1[3]}};
            S[j][0] = 0.f; S[j][1] = 0.f; S[j][2] = 0.f; S[j][3] = 0.f;
            uint32_t Clo[2] = {0u, 0u};
            #pragma unroll
            for (int k = 0; k < 4; ++k) {
                mma16816(S[j], aH[k], bh[k]);
                mma16816h(Clo, aH[k], bl[k]);
            }
            const float2 c01 = __half22float2(*(__half2*)&Clo[0]);
            const float2 c23 = __half22float2(*(__half2*)&Clo[1]);
            S[j][0] += c01.x; S[j][1] += c01.y;
            S[j][2] += c23.x; S[j][3] += c23.y;
        }

        // ---- online softmax (rows: ra = lane/4, rb = ra+8) ----
        float mx0 = -1e30f, mx1 = -1e30f;
        #pragma unroll
        for (int j = 0; j < 8; ++j) {
            mx0 = fmaxf(mx0, fmaxf(S[j][0], S[j][1]));
            mx1 = fmaxf(mx1, fmaxf(S[j][2], S[j][3]));
        }
        mx0 = fmaxf(mx0, __shfl_xor_sync(0xffffffffu, mx0, 1));
        mx0 = fmaxf(mx0, __shfl_xor_sync(0xffffffffu, mx0, 2));
        mx1 = fmaxf(mx1, __shfl_xor_sync(0xffffffffu, mx1, 1));
        mx1 = fmaxf(mx1, __shfl_xor_sync(0xffffffffu, mx1, 2));
        const float mn0 = fmaxf(m0, mx0), mn1 = fmaxf(m1, mx1);
        const float cr0 = __expf(m0 - mn0), cr1 = __expf(m1 - mn1);
        m0 = mn0; m1 = mn1;

        float s0 = 0.f, s1 = 0.f;
        uint32_t Ph[8][2];
        #pragma unroll
        for (int j = 0; j < 8; ++j) {
            float p0 = __expf(S[j][0] - mn0), p1 = __expf(S[j][1] - mn0);
            float p2 = __expf(S[j][2] - mn1), p3 = __expf(S[j][3] - mn1);
            s0 += p0 + p1; s1 += p2 + p3;
            __half2 H0 = __floats2half2_rn(p0, p1), H1 = __floats2half2_rn(p2, p3);
            Ph[j][0] = *(uint32_t*)&H0; Ph[j][1] = *(uint32_t*)&H1;
        }
        s0 += __shfl_xor_sync(0xffffffffu, s0, 1);
        s0 += __shfl_xor_sync(0xffffffffu, s0, 2);
        s1 += __shfl_xor_sync(0xffffffffu, s1, 1);
        s1 += __shfl_xor_sync(0xffffffffu, s1, 2);
        l0 = l0 * cr0 + s0; l1 = l1 * cr1 + s1;
        #pragma unroll
        for (int jc = 0; jc < 8; ++jc) {
            O[jc][0] *= cr0; O[jc][1] *= cr0; O[jc][2] *= cr1; O[jc][3] *= cr1;
        }

        // ---- GEMM2: O[16 rows][64 ch] += Ph[16][64] * Vh[64][64] ----
        #pragma unroll
        for (int jc = 0; jc < 8; ++jc) {
            uint32_t vh[4][2];
            #pragma unroll
            for (int kp = 0; kp < 2; ++kp) {
                uint32_t t[4];
                const int key = kp * 32 + g * 8 + lr;
                ldsm4t(swz(XH, key, jc * 16), t);
                vh[2*kp][0] = t[0]; vh[2*kp][1] = t[1];
                vh[2*kp+1][0] = t[2]; vh[2*kp+1][1] = t[3];
            }
            #pragma unroll
            for (int kk = 0; kk < 4; ++kk) {
                uint32_t Ah[4] = {Ph[2*kk][0], Ph[2*kk][1], Ph[2*kk+1][0], Ph[2*kk+1][1]};
                mma16816(O[jc], Ah, vh[kk]);
            }
        }
        __syncthreads();   // all warps done with this buffer before it is overwritten
    }

    // ---- write per-split partials (O in fp16) ----
    const int ra = qb + r0 + (lane >> 2);
    const size_t pb = (size_t)(b * KSPLIT + kh) * NSEQ;
    if ((lane & 3) == 0) {
        g_mpart[pb + ra] = m0;     g_lpart[pb + ra] = l0;
        g_mpart[pb + ra + 8] = m1; g_lpart[pb + ra + 8] = l1;
    }
    #pragma unroll
    for (int jc = 0; jc < 8; ++jc) {
        const int ch = jc * 8 + 2 * (lane & 3);
        __half2 a = __floats2half2_rn(O[jc][0], O[jc][1]);
        __half2 c = __floats2half2_rn(O[jc][2], O[jc][3]);
        *(__half2*)&g_Opart[(pb + ra) * CDIM + ch]     = a;
        *(__half2*)&g_Opart[(pb + ra + 8) * CDIM + ch] = c;
    }
}

__global__ __launch_bounds__(256) void merge_kernel(const float* __restrict__ x,
                                                    const float* __restrict__ gamma,
                                                    float* __restrict__ out)
{
    const int i = blockIdx.x * 256 + threadIdx.x;      // 131072 float4s total
    const int c4 = i & 15;
    const int r  = (i >> 4) & (NSEQ - 1);
    const int b  = i >> 16;

    float mv[KSPLIT];
    float M = -1e30f;
    #pragma unroll
    for (int s = 0; s < KSPLIT; ++s) {
        mv[s] = g_mpart[(size_t)(b * KSPLIT + s) * NSEQ + r];
        M = fmaxf(M, mv[s]);
    }
    float den = 0.f;
    float4 acc = make_float4(0.f, 0.f, 0.f, 0.f);
    #pragma unroll
    for (int s = 0; s < KSPLIT; ++s) {
        const size_t p = (size_t)(b * KSPLIT + s) * NSEQ + r;
        const float ws = __expf(mv[s] - M);
        den += ws * g_lpart[p];
        const __half2* oh = (const __half2*)&g_Opart[p * CDIM + c4 * 4];
        const float2 o01 = __half22float2(oh[0]);
        const float2 o23 = __half22float2(oh[1]);
        acc.x += ws * o01.x; acc.y += ws * o01.y;
        acc.z += ws * o23.x; acc.w += ws * o23.y;
    }
    const float4 xv = ((const float4*)&x[((size_t)b * NSEQ + r) * CDIM])[c4];
    const float gg = gamma[0], inv = 1.0f / den;
    float4 o;
    o.x = gg * acc.x * inv + xv.x;
    o.y = gg * acc.y * inv + xv.y;
    o.z = gg * acc.z * inv + xv.z;
    o.w = gg * acc.w * inv + xv.w;
    ((float4*)&out[((size_t)b * NSEQ + r) * CDIM])[c4] = o;
}

extern "C" void kernel_launch(void* const* d_in, const int* in_sizes, int n_in,
                              void* d_out, int out_size)
{
    const float* x     = (const float*)d_in[0];
    const float* gamma = (const float*)d_in[1];
    float* out = (float*)d_out;
    (void)in_sizes; (void)n_in; (void)out_size;

    cudaFuncSetAttribute(attn_main, cudaFuncAttributeMaxDynamicSharedMemorySize, SMEM_BYTES);
    split_kernel<<<512, 256>>>(x);
    attn_main<<<dim3(NSEQ / MT, 2, KSPLIT), 128, SMEM_BYTES>>>();
    merge_kernel<<<512, 256>>>(x, gamma, out);
}

// round 15
// speedup vs baseline: 2.2046x; 1.3954x over previous
#include <cuda_runtime.h>
#include <cuda_fp16.h>
#include <math.h>
#include <stdint.h>

#define NSEQ  4096
#define CDIM  64
#define MT    64
#define KB    64
#define KSPLIT 8
#define KHALF (NSEQ / KSPLIT)      // 512
#define NBLK  (KHALF / KB)         // 8

// scratch (allocation-free rule -> __device__ globals)
__device__ __half g_xh[2 * NSEQ * CDIM];
__device__ __half g_Opart[2 * KSPLIT * NSEQ * CDIM];
__device__ float  g_lpart[2 * KSPLIT * NSEQ];
__device__ float  g_mpart[2 * KSPLIT * NSEQ];

// smem layout (bytes): QH 64x128B (8KB); X hi double-buffered 64x128B (8KB per buf)
#define QH_OFF 0u
#define XB_OFF 8192u               // buf b at XB_OFF + b*8192
#define SMEM_BYTES 24576u          // 24KB -> 4 CTAs/SM (reg-capped)

__device__ __forceinline__ uint32_t cvta_smem(const void* p) {
    uint32_t a;
    asm("{ .reg .u64 t; cvta.to.shared.u64 t, %1; cvt.u32.u64 %0, t; }" : "=r"(a) : "l"(p));
    return a;
}
__device__ __forceinline__ void ldsm4(uint32_t addr, uint32_t* r) {
    asm volatile("ldmatrix.sync.aligned.m8n8.x4.shared.b16 {%0,%1,%2,%3}, [%4];"
                 : "=r"(r[0]), "=r"(r[1]), "=r"(r[2]), "=r"(r[3]) : "r"(addr));
}
__device__ __forceinline__ void ldsm4t(uint32_t addr, uint32_t* r) {
    asm volatile("ldmatrix.sync.aligned.m8n8.x4.trans.shared.b16 {%0,%1,%2,%3}, [%4];"
                 : "=r"(r[0]), "=r"(r[1]), "=r"(r[2]), "=r"(r[3]) : "r"(addr));
}
__device__ __forceinline__ void mma16816(float* c, const uint32_t* a, const uint32_t* b) {
    asm volatile("mma.sync.aligned.m16n8k16.row.col.f32.f16.f16.f32 "
                 "{%0,%1,%2,%3}, {%4,%5,%6,%7}, {%8,%9}, {%0,%1,%2,%3};"
                 : "+f"(c[0]), "+f"(c[1]), "+f"(c[2]), "+f"(c[3])
                 : "r"(a[0]), "r"(a[1]), "r"(a[2]), "r"(a[3]), "r"(b[0]), "r"(b[1]));
}
__device__ __forceinline__ void cp16(uint32_t dst, const void* src) {
    asm volatile("cp.async.cg.shared.global [%0], [%1], 16;" :: "r"(dst), "l"(src));
}
#define CP_COMMIT()  asm volatile("cp.async.commit_group;" ::: "memory")
#define CP_WAIT(n)   asm volatile("cp.async.wait_group %0;" :: "n"(n) : "memory")

// XOR-swizzled byte offset inside a 128B-row tile
__device__ __forceinline__ uint32_t swz(uint32_t tb, int row, int cb) {
    return tb + row * 128 + (((((unsigned)cb >> 4) ^ (row & 7)) << 4) | (cb & 15));
}

// ---- pre-pass: cast fp32 x to fp16 hi ----
__global__ __launch_bounds__(256) void split_kernel(const float* __restrict__ x)
{
    const int i = blockIdx.x * 256 + threadIdx.x;   // 131072 float4s
    float4 v = ((const float4*)x)[i];
    __half2 H0 = __floats2half2_rn(v.x, v.y), H1 = __floats2half2_rn(v.z, v.w);
    ((uint2*)g_xh)[i] = make_uint2(*(uint32_t*)&H0, *(uint32_t*)&H1);
}

__global__ __launch_bounds__(128, 4) void attn_main()
{
    extern __shared__ char sm[];
    const uint32_t sb = cvta_smem(sm);
    const int tid = threadIdx.x, lane = tid & 31, w = tid >> 5;
    const int qb = blockIdx.x * MT, b = blockIdx.y, kh = blockIdx.z;
    const __half* xh = g_xh + (size_t)b * NSEQ * CDIM;

    // prologue: Q hi + X block 0 via cp.async (one group)
    {
        const int row = tid >> 1, h = tid & 1;
        const size_t qrow = (size_t)(qb + row) * CDIM + h * 32;
        const size_t xrow = (size_t)(kh * KHALF + row) * CDIM + h * 32;
        #pragma unroll
        for (int i = 0; i < 4; ++i) {
            const int cb = h * 64 + i * 16;     // byte col within 128B row
            cp16(swz(sb + QH_OFF, row, cb), xh + qrow + i * 8);
            cp16(swz(sb + XB_OFF, row, cb), xh + xrow + i * 8);
        }
        CP_COMMIT();
    }
    CP_WAIT(0);
    __syncthreads();

    const int r0 = w * 16;
    const int g = lane >> 3, lr = lane & 7;

    // ---- hoisted Q-hi fragments (loop-invariant; QH never overwritten) ----
    uint32_t aH[4][4];
    {
        const int arow = r0 + (g & 1) * 8 + lr;
        const int acb  = (g >> 1) * 16;
        #pragma unroll
        for (int k = 0; k < 4; ++k)
            ldsm4(swz(sb + QH_OFF, arow, k * 32 + acb), aH[k]);
    }

    float m0 = -1e30f, m1 = -1e30f, l0 = 0.f, l1 = 0.f;
    float O[8][4];
    #pragma unroll
    for (int jc = 0; jc < 8; ++jc)
        #pragma unroll
        for (int q = 0; q < 4; ++q) O[jc][q] = 0.f;

    for (int blk = 0; blk < NBLK; ++blk) {
        const uint32_t XH = sb + XB_OFF + (blk & 1) * 8192u;

        // issue next block's loads into the other buffer
        if (blk + 1 < NBLK) {
            const uint32_t NH = sb + XB_OFF + ((blk + 1) & 1) * 8192u;
            const int row = tid >> 1, h = tid & 1;
            const size_t xrow = (size_t)(kh * KHALF + (blk + 1) * KB + row) * CDIM + h * 32;
            #pragma unroll
            for (int i = 0; i < 4; ++i)
                cp16(swz(NH, row, h * 64 + i * 16), xh + xrow + i * 8);
            CP_COMMIT();
            CP_WAIT(1);
        } else {
            CP_WAIT(0);
        }
        __syncthreads();

        // ---- GEMM1: S = Qh * Xh (pure fp16 operands, f32 acc) ----
        float S[8][4];
        #pragma unroll
        for (int j = 0; j < 8; ++j) {
            const int krow = j * 8 + lr;
            uint32_t t0[4], t1[4];
            ldsm4(swz(XH, krow, g * 16), t0);
            ldsm4(swz(XH, krow, 64 + g * 16), t1);
            uint32_t bh[4][2] = {{t0[0],t0[1]},{t0[2],t0[3]},{t1[0],t1[1]},{t1[2],t1[3]}};
            S[j][0] = 0.f; S[j][1] = 0.f; S[j][2] = 0.f; S[j][3] = 0.f;
            #pragma unroll
            for (int k = 0; k < 4; ++k)
                mma16816(S[j], aH[k], bh[k]);
        }

        // ---- online softmax (rows: ra = lane/4, rb = ra+8) ----
        float mx0 = -1e30f, mx1 = -1e30f;
        #pragma unroll
        for (int j = 0; j < 8; ++j) {
            mx0 = fmaxf(mx0, fmaxf(S[j][0], S[j][1]));
            mx1 = fmaxf(mx1, fmaxf(S[j][2], S[j][3]));
        }
        mx0 = fmaxf(mx0, __shfl_xor_sync(0xffffffffu, mx0, 1));
        mx0 = fmaxf(mx0, __shfl_xor_sync(0xffffffffu, mx0, 2));
        mx1 = fmaxf(mx1, __shfl_xor_sync(0xffffffffu, mx1, 1));
        mx1 = fmaxf(mx1, __shfl_xor_sync(0xffffffffu, mx1, 2));
        const float mn0 = fmaxf(m0, mx0), mn1 = fmaxf(m1, mx1);
        const float cr0 = __expf(m0 - mn0), cr1 = __expf(m1 - mn1);
        m0 = mn0; m1 = mn1;

        float s0 = 0.f, s1 = 0.f;
        uint32_t Ph[8][2];
        #pragma unroll
        for (int j = 0; j < 8; ++j) {
            float p0 = __expf(S[j][0] - mn0), p1 = __expf(S[j][1] - mn0);
            float p2 = __expf(S[j][2] - mn1), p3 = __expf(S[j][3] - mn1);
            s0 += p0 + p1; s1 += p2 + p3;
            __half2 H0 = __floats2half2_rn(p0, p1), H1 = __floats2half2_rn(p2, p3);
            Ph[j][0] = *(uint32_t*)&H0; Ph[j][1] = *(uint32_t*)&H1;
        }
        s0 += __shfl_xor_sync(0xffffffffu, s0, 1);
        s0 += __shfl_xor_sync(0xffffffffu, s0, 2);
        s1 += __shfl_xor_sync(0xffffffffu, s1, 1);
        s1 += __shfl_xor_sync(0xffffffffu, s1, 2);
        l0 = l0 * cr0 + s0; l1 = l1 * cr1 + s1;
        #pragma unroll
        for (int jc = 0; jc < 8; ++jc) {
            O[jc][0] *= cr0; O[jc][1] *= cr0; O[jc][2] *= cr1; O[jc][3] *= cr1;
        }

        // ---- GEMM2: O[16 rows][64 ch] += Ph[16][64] * Vh[64][64] ----
        #pragma unroll
        for (int jc = 0; jc < 8; ++jc) {
            uint32_t vh[4][2];
            #pragma unroll
            for (int kp = 0; kp < 2; ++kp) {
                uint32_t t[4];
                const int key = kp * 32 + g * 8 + lr;
                ldsm4t(swz(XH, key, jc * 16), t);
                vh[2*kp][0] = t[0]; vh[2*kp][1] = t[1];
                vh[2*kp+1][0] = t[2]; vh[2*kp+1][1] = t[3];
            }
            #pragma unroll
            for (int kk = 0; kk < 4; ++kk) {
                uint32_t Ah[4] = {Ph[2*kk][0], Ph[2*kk][1], Ph[2*kk+1][0], Ph[2*kk+1][1]};
                mma16816(O[jc], Ah, vh[kk]);
            }
        }
        __syncthreads();   // all warps done with this buffer before it is overwritten
    }

    // ---- write per-split partials (O in fp16) ----
    const int ra = qb + r0 + (lane >> 2);
    const size_t pb = (size_t)(b * KSPLIT + kh) * NSEQ;
    if ((lane & 3) == 0) {
        g_mpart[pb + ra] = m0;     g_lpart[pb + ra] = l0;
        g_mpart[pb + ra + 8] = m1; g_lpart[pb + ra + 8] = l1;
    }
    #pragma unroll
    for (int jc = 0; jc < 8; ++jc) {
        const int ch = jc * 8 + 2 * (lane & 3);
        __half2 a = __floats2half2_rn(O[jc][0], O[jc][1]);
        __half2 c = __floats2half2_rn(O[jc][2], O[jc][3]);
        *(__half2*)&g_Opart[(pb + ra) * CDIM + ch]     = a;
        *(__half2*)&g_Opart[(pb + ra + 8) * CDIM + ch] = c;
    }
}

__global__ __launch_bounds__(256) void merge_kernel(const float* __restrict__ x,
                                                    const float* __restrict__ gamma,
                                                    float* __restrict__ out)
{
    const int i = blockIdx.x * 256 + threadIdx.x;      // 131072 float4s total
    const int c4 = i & 15;
    const int r  = (i >> 4) & (NSEQ - 1);
    const int b  = i >> 16;

    float mv[KSPLIT];
    float M = -1e30f;
    #pragma unroll
    for (int s = 0; s < KSPLIT; ++s) {
        mv[s] = g_mpart[(size_t)(b * KSPLIT + s) * NSEQ + r];
        M = fmaxf(M, mv[s]);
    }
    float den = 0.f;
    float4 acc = make_float4(0.f, 0.f, 0.f, 0.f);
    #pragma unroll
    for (int s = 0; s < KSPLIT; ++s) {
        const size_t p = (size_t)(b * KSPLIT + s) * NSEQ + r;
        const float ws = __expf(mv[s] - M);
        den += ws * g_lpart[p];
        const __half2* oh = (const __half2*)&g_Opart[p * CDIM + c4 * 4];
        const float2 o01 = __half22float2(oh[0]);
        const float2 o23 = __half22float2(oh[1]);
        acc.x += ws * o01.x; acc.y += ws * o01.y;
        acc.z += ws * o23.x; acc.w += ws * o23.y;
    }
    const float4 xv = ((const float4*)&x[((size_t)b * NSEQ + r) * CDIM])[c4];
    const float gg = gamma[0], inv = 1.0f / den;
    float4 o;
    o.x = gg * acc.x * inv + xv.x;
    o.y = gg * acc.y * inv + xv.y;
    o.z = gg * acc.z * inv + xv.z;
    o.w = gg * acc.w * inv + xv.w;
    ((float4*)&out[((size_t)b * NSEQ + r) * CDIM])[c4] = o;
}

extern "C" void kernel_launch(void* const* d_in, const int* in_sizes, int n_in,
                              void* d_out, int out_size)
{
    const float* x     = (const float*)d_in[0];
    const float* gamma = (const float*)d_in[1];
    float* out = (float*)d_out;
    (void)in_sizes; (void)n_in; (void)out_size;

    cudaFuncSetAttribute(attn_main, cudaFuncAttributeMaxDynamicSharedMemorySize, SMEM_BYTES);
    split_kernel<<<512, 256>>>(x);
    attn_main<<<dim3(NSEQ / MT, 2, KSPLIT), 128, SMEM_BYTES>>>();
    merge_kernel<<<512, 256>>>(x, gamma, out);
}